// round 10
// baseline (speedup 1.0000x reference)
#include <cuda_runtime.h>

#define BB 4
#define HH 480
#define WW 640
#define HWp (HH * WW)
#define NPIX (BB * HWp)

// Tile geometry
#define TW 64           // tile width (pixels)
#define TH 8            // tile height (pixels)
#define HALO 8
#define SW (TW + 2*HALO + 1)   // 81 staged cols
#define SH (TH + 2*HALO + 1)   // 25 staged rows

// Scratch (static __device__ arrays — no allocation)
__device__ float  g_aff[9 * NPIX];    // normalized affinities, plane layout
__device__ float2 g_off[8 * NPIX];    // packed (dy,dx) per tap, plane layout
__device__ float  g_wA [NPIX];        // (1-m)*confidence
__device__ float  g_ping[NPIX];
__device__ float  g_pong[NPIX];

// ---------------------------------------------------------------------------
// Pass A: affinity normalization (tanh once) + offset packing + wA + initial g
// ---------------------------------------------------------------------------
__global__ void __launch_bounds__(256)
precompute_kernel(const float* __restrict__ feat_init,
                  const float* __restrict__ guidance,
                  const float* __restrict__ confidence,
                  const float* __restrict__ feat_fix,
                  const float* __restrict__ aff_scale) {
    int idx = blockIdx.x * blockDim.x + threadIdx.x;
    if (idx >= NPIX) return;
    int b = idx / HWp;
    int p = idx - b * HWp;

    const float* gbase = guidance + (size_t)b * 24 * HWp + p;

#pragma unroll
    for (int t = 0; t < 8; t++) {
        float dy = gbase[(size_t)(2 * t) * HWp];
        float dx = gbase[(size_t)(2 * t + 1) * HWp];
        g_off[(size_t)(b * 8 + t) * HWp + p] = make_float2(dy, dx);
    }

    const float* gp = gbase + (size_t)16 * HWp;
    float scale = aff_scale[0] + 1e-8f;
    float a[8];
    float s = 1e-4f;
#pragma unroll
    for (int j = 0; j < 8; j++) {
        a[j] = tanhf(gp[(size_t)j * HWp]) / scale;
        s += fabsf(a[j]);
    }
    s = fmaxf(s, 1.0f);
    float inv = 1.0f / s;
    float sum = 0.0f;
#pragma unroll
    for (int j = 0; j < 8; j++) { a[j] *= inv; sum += a[j]; }
    float aref = 1.0f - sum;

    float* ap = g_aff + (size_t)b * 9 * HWp + p;
#pragma unroll
    for (int j = 0; j < 4; j++) ap[(size_t)j * HWp] = a[j];
    ap[(size_t)4 * HWp] = aref;
#pragma unroll
    for (int j = 4; j < 8; j++) ap[(size_t)(j + 1) * HWp] = a[j];

    float ff = feat_fix[idx];
    float fi = feat_init[idx];
    float cf = confidence[idx];
    bool m = ff > 0.0f;
    float conf = m ? 1.0f : cf;
    float feat = m ? ff : fi;
    g_wA[idx]  = m ? 0.0f : cf;
    g_ping[idx] = feat * conf;
}

// ---------------------------------------------------------------------------
// Fallback: global-memory bilinear with zero-outside semantics (rare path)
// ---------------------------------------------------------------------------
__device__ __noinline__ float bil_global(const float* __restrict__ img,
                                         float py, float px) {
    float y0f = floorf(py);
    float x0f = floorf(px);
    int y0 = (int)y0f;
    int x0 = (int)x0f;
    float wy = py - y0f;
    float wx = px - x0f;

    float w00 = (1.0f - wy) * (1.0f - wx);
    float w01 = (1.0f - wy) * wx;
    float w10 = wy * (1.0f - wx);
    float w11 = wy * wx;

    bool vy0 = (unsigned)y0 < (unsigned)HH;
    bool vy1 = (unsigned)(y0 + 1) < (unsigned)HH;
    bool vx0 = (unsigned)x0 < (unsigned)WW;
    bool vx1 = (unsigned)(x0 + 1) < (unsigned)WW;

    w00 = (vy0 && vx0) ? w00 : 0.0f;
    w01 = (vy0 && vx1) ? w01 : 0.0f;
    w10 = (vy1 && vx0) ? w10 : 0.0f;
    w11 = (vy1 && vx1) ? w11 : 0.0f;

    int cy0 = min(max(y0, 0), HH - 1);
    int cy1 = min(max(y0 + 1, 0), HH - 1);
    int cx0 = min(max(x0, 0), WW - 1);
    int cx1 = min(max(x0 + 1, 0), WW - 1);

    const float* r0 = img + (size_t)cy0 * WW;
    const float* r1 = img + (size_t)cy1 * WW;
    float samp = w00 * r0[cx0];
    samp = fmaf(w01, r0[cx1], samp);
    samp = fmaf(w10, r1[cx0], samp);
    samp = fmaf(w11, r1[cx1], samp);
    return samp;
}

// ---------------------------------------------------------------------------
// Bilinear from staged smem tile (zeros pre-written outside image => no masks)
// sy0/sx0 are coords relative to staged origin. Caller guarantees in-window.
// ---------------------------------------------------------------------------
__device__ __forceinline__ float bil_smem(const float tile[SH][SW],
                                          float py, float px,
                                          int oy, int ox) {
    float y0f = floorf(py);
    float x0f = floorf(px);
    float wy = py - y0f;
    float wx = px - x0f;
    int sy = (int)y0f - oy;
    int sx = (int)x0f - ox;

    float v00 = tile[sy][sx];
    float v01 = tile[sy][sx + 1];
    float v10 = tile[sy + 1][sx];
    float v11 = tile[sy + 1][sx + 1];

    float top = fmaf(wx, v01 - v00, v00);
    float bot = fmaf(wx, v11 - v10, v10);
    return fmaf(wy, bot - top, top);
}

// Exact-form weights variant to match reference arithmetic closely:
__device__ __forceinline__ float bil_smem_exact(const float tile[SH][SW],
                                                float py, float px,
                                                int oy, int ox) {
    float y0f = floorf(py);
    float x0f = floorf(px);
    float wy = py - y0f;
    float wx = px - x0f;
    int sy = (int)y0f - oy;
    int sx = (int)x0f - ox;

    float w00 = (1.0f - wy) * (1.0f - wx);
    float w01 = (1.0f - wy) * wx;
    float w10 = wy * (1.0f - wx);
    float w11 = wy * wx;

    float samp = w00 * tile[sy][sx];
    samp = fmaf(w01, tile[sy][sx + 1], samp);
    samp = fmaf(w10, tile[sy + 1][sx], samp);
    samp = fmaf(w11, tile[sy + 1][sx + 1], samp);
    return samp;
}

// ---------------------------------------------------------------------------
// Propagation step, smem-staged gathers. Grid: (10, 60, 2) blocks, 256 thr.
// Each block: 64x8 pixel tile, 2 px per thread (lanes span one row).
// ---------------------------------------------------------------------------
__global__ void __launch_bounds__(256)
prop_kernel(const float* __restrict__ feat_fix,
            const float* __restrict__ gin,
            float* __restrict__ gout,
            int last, int b0) {
    __shared__ float tile[SH][SW];

    int b   = b0 + blockIdx.z;
    int ty0 = blockIdx.y * TH;       // tile origin y
    int tx0 = blockIdx.x * TW;       // tile origin x
    int oy  = ty0 - HALO;            // staged origin
    int ox  = tx0 - HALO;

    const float* img = gin + (size_t)b * HWp;

    // ---- Stage g tile with zero padding outside image ----
    for (int i = threadIdx.x; i < SH * SW; i += 256) {
        int r = i / SW;
        int c = i - r * SW;
        int gy = oy + r;
        int gx = ox + c;
        float v = 0.0f;
        if ((unsigned)gy < (unsigned)HH && (unsigned)gx < (unsigned)WW)
            v = img[(size_t)gy * WW + gx];
        tile[r][c] = v;
    }
    __syncthreads();

    // ---- Pixel mapping: thread t -> row t/32, cols 2*(t%32), 2*(t%32)+1 ----
    int row = threadIdx.x >> 5;
    int cp  = (threadIdx.x & 31) * 2;
    int y   = ty0 + row;
    int x0r = tx0 + cp;
    int x1r = x0r + 1;
    int p   = y * WW + x0r;          // even
    int gbase = b * HWp + p;

    const float2* offp = g_off + (size_t)b * 8 * HWp + p;
    const float*  affp = g_aff + (size_t)b * 9 * HWp + p;

    const int kyv[8] = {-1, -1, -1, 0, 0, 1, 1, 1};
    const int kxv[8] = {-1, 0, 1, -1, 1, -1, 0, 1};

    float acc0 = 0.0f, acc1 = 0.0f;

#pragma unroll
    for (int t = 0; t < 8; t++) {
        float4 o = *reinterpret_cast<const float4*>(offp + (size_t)t * HWp);
        int j = (t < 4) ? t : (t + 1);
        float2 a = *reinterpret_cast<const float2*>(affp + (size_t)j * HWp);

        float py0 = (float)(y + kyv[t]) + o.x;
        float px0 = (float)(x0r + kxv[t]) + o.y;
        float py1 = (float)(y + kyv[t]) + o.z;
        float px1 = (float)(x1r + kxv[t]) + o.w;

        // window check (always true unless |offset| > ~7)
        float s0, s1;
        {
            int sy = (int)floorf(py0) - oy;
            int sx = (int)floorf(px0) - ox;
            if ((unsigned)sy < (unsigned)(SH - 1) && (unsigned)sx < (unsigned)(SW - 1))
                s0 = bil_smem_exact(tile, py0, px0, oy, ox);
            else
                s0 = bil_global(img, py0, px0);
        }
        {
            int sy = (int)floorf(py1) - oy;
            int sx = (int)floorf(px1) - ox;
            if ((unsigned)sy < (unsigned)(SH - 1) && (unsigned)sx < (unsigned)(SW - 1))
                s1 = bil_smem_exact(tile, py1, px1, oy, ox);
            else
                s1 = bil_global(img, py1, px1);
        }
        acc0 = fmaf(a.x, s0, acc0);
        acc1 = fmaf(a.y, s1, acc1);
    }

    // center tap (offset exactly zero -> direct read from staged tile)
    {
        float2 ac = *reinterpret_cast<const float2*>(affp + (size_t)4 * HWp);
        float gc0 = tile[row + HALO][cp + HALO];
        float gc1 = tile[row + HALO][cp + 1 + HALO];
        acc0 = fmaf(ac.x, gc0, acc0);
        acc1 = fmaf(ac.y, gc1, acc1);
    }

    float2 ffv = *reinterpret_cast<const float2*>(feat_fix + gbase);
    float2 w;
    if (last) {
        w.x = (ffv.x > 0.0f) ? 0.0f : 1.0f;
        w.y = (ffv.y > 0.0f) ? 0.0f : 1.0f;
    } else {
        w = *reinterpret_cast<const float2*>(g_wA + gbase);
    }

    float2 r;
    r.x = fmaf(w.x, acc0, ffv.x);
    r.y = fmaf(w.y, acc1, ffv.y);
    *reinterpret_cast<float2*>(gout + gbase) = r;
}

// ---------------------------------------------------------------------------
extern "C" void kernel_launch(void* const* d_in, const int* in_sizes, int n_in,
                              void* d_out, int out_size) {
    const float* feat_init  = (const float*)d_in[0];
    const float* guidance   = (const float*)d_in[1];
    const float* confidence = (const float*)d_in[2];
    const float* feat_fix   = (const float*)d_in[3];
    const float* aff_scale  = (const float*)d_in[4];
    float* out = (float*)d_out;

    float* ping = nullptr;
    float* pong = nullptr;
    cudaGetSymbolAddress((void**)&ping, g_ping);
    cudaGetSymbolAddress((void**)&pong, g_pong);

    const int threads = 256;
    const int blocksA = (NPIX + threads - 1) / threads;
    dim3 gridP(WW / TW, HH / TH, 2);   // (10, 60, 2)

    precompute_kernel<<<blocksA, threads>>>(feat_init, guidance, confidence,
                                            feat_fix, aff_scale);

    // Batch groups {0,1} then {2,3}: group invariants (~52 MB) stay L2-resident
    for (int b0 = 0; b0 < BB; b0 += 2) {
        float* cur = ping;
        float* nxt = pong;
        for (int i = 1; i <= 17; i++) {
            prop_kernel<<<gridP, threads>>>(feat_fix, cur, nxt, /*last=*/0, b0);
            float* t = cur; cur = nxt; nxt = t;
        }
        prop_kernel<<<gridP, threads>>>(feat_fix, cur, out, /*last=*/1, b0);
    }
}